// round 4
// baseline (speedup 1.0000x reference)
#include <cuda_runtime.h>
#include <cstdint>
#include <cstddef>

// Problem constants
#define NB   8
#define CB   128
#define NC   1024          // NB*CB
#define HH   160
#define WW   160
#define NA   180
#define NR   180
#define AR   (NA*NR)       // 32400
#define PIX  (HH*WW)       // 25600
#define WROWS 20           // staged rho-window (max true span is 18)

// Scratch in __device__ globals (no allocation allowed)
__device__ float         g_T[(size_t)AR * NC];       // transposed: T[a][r][nc]
__device__ unsigned char g_idx[(size_t)NA * PIX];    // r index table [a][y][x]
__device__ double        g_tab[2 * NA];              // cos/irho, sin/irho

// ---------------------------------------------------------------------------
// Kernel 0: trig table (fp64, once)
// ---------------------------------------------------------------------------
__global__ void tab_kernel()
{
    int a = threadIdx.x;
    if (a < NA) {
        const double PI = 3.14159265358979323846;
        double th = (double)a * (PI / 180.0);
        double irho = 227.0 / 180.0;   // (int(sqrt(160^2+160^2))+1)/180
        g_tab[a]      = cos(th) / irho;
        g_tab[NA + a] = sin(th) / irho;
    }
}

// ---------------------------------------------------------------------------
// Kernel 1: rho-index table (fp64 FMA-class ops only; matches numpy exactly)
// ---------------------------------------------------------------------------
__global__ void build_idx_kernel()
{
    const int a = blockIdx.y;
    double tc = g_tab[a], ts = g_tab[NA + a];
    int p = blockIdx.x * 256 + threadIdx.x;
    int y = p / WW, x = p - y * WW;
    double v = __dadd_rn(__dmul_rn((double)(x - 80), tc),
                         __dmul_rn((double)(y - 80), ts));
    int r = (int)rint(v) + 90;
    r = min(NR - 1, max(0, r));
    g_idx[(size_t)a * PIX + p] = (unsigned char)r;
}

// ---------------------------------------------------------------------------
// Kernel 2: transpose In[NC][AR] -> T[AR][NC]
// ---------------------------------------------------------------------------
__global__ void transpose_kernel(const float* __restrict__ in)
{
    __shared__ float tile[32][33];
    int ar0 = blockIdx.x * 32;
    int nc0 = blockIdx.y * 32;
    int tx = threadIdx.x;
    int ty = threadIdx.y;
    #pragma unroll
    for (int i = ty; i < 32; i += 8) {
        int ar = ar0 + tx;
        if (ar < AR) tile[i][tx] = in[(size_t)(nc0 + i) * AR + ar];
    }
    __syncthreads();
    #pragma unroll
    for (int i = ty; i < 32; i += 8) {
        int ar = ar0 + i;
        if (ar < AR) g_T[(size_t)ar * NC + nc0 + tx] = tile[tx][i];
    }
}

// ---------------------------------------------------------------------------
// Kernel 3: main inverse-Hough accumulation.
//   CTA: 16x16 pixel tile x 128-ch group, 512 thr / 16 warps.
//   Warp = 4x4 pixel subtile; lanes = 32 x 4 consecutive channels.
//   cp.async 4-deep smem row pipeline; consume along line-direction
//   serpentine with a SOFTWARE-PIPELINED double-buffered row value:
//   the (predicated) LDS for step i+1 is issued before the adds of step i,
//   putting ~24-32 interleaved cycles between LDS and its consumer.
// ---------------------------------------------------------------------------
__device__ __forceinline__ void cp16(unsigned smem_addr, const void* gptr)
{
    asm volatile("cp.async.cg.shared.global [%0], [%1], 16;\n"
                 :: "r"(smem_addr), "l"(gptr));
}

__global__ void __launch_bounds__(512, 1) iht_main_kernel(float* __restrict__ out)
{
    __shared__ __align__(16) char sbuf[4][WROWS * 512];          // 40960 B
    __shared__ __align__(16) unsigned char sidx[NA * 256];       // 46080 B
    __shared__ unsigned smeta[NA];                               // base | nch<<16

    const int tid = threadIdx.x;
    const int x0 = blockIdx.x * 16;
    const int y0 = blockIdx.y * 16;
    const int cz0 = blockIdx.z * 128;
    const int lane = tid & 31;
    const int c0 = cz0 + lane * 4;

    const int w  = tid >> 5;
    const int sy = (w >> 2) << 2;
    const int sx = (w & 3) << 2;

    // ---- stage idx tile to smem ----
    for (int i = tid; i < NA * 16; i += 512) {
        int a = i >> 4, py = i & 15;
        ((uint4*)sidx)[i] =
            *(const uint4*)(g_idx + (size_t)a * PIX + (y0 + py) * WW + x0);
    }
    __syncthreads();

    // ---- per-angle meta ----
    for (int a = tid; a < NA; a += 512) {
        const unsigned char* s = sidx + a * 256;
        int r00 = s[0], r01 = s[15], r10 = s[240], r11 = s[255];
        int rmin = min(min(r00, r01), min(r10, r11));
        int rmax = max(max(r00, r01), max(r10, r11));
        int base = min(rmin, NR - WROWS);
        int nch  = (rmax - base + 1) << 5;
        smeta[a] = (unsigned)base | ((unsigned)nch << 16);
    }
    __syncthreads();

    // ---- staging ----
    auto stage = [&](int a3) {
        unsigned m = smeta[a3];
        int base = m & 0xffff;
        int nch  = m >> 16;
        const float* src = g_T + ((size_t)a3 * NR + base) * NC + cz0;
        unsigned sdst = (unsigned)__cvta_generic_to_shared(sbuf[a3 & 3]);
        if (tid < nch)
            cp16(sdst + (tid << 4), src + ((tid >> 5) << 10) + ((tid & 31) << 2));
        int c = tid + 512;
        if (tid < 128 && c < nch)
            cp16(sdst + (c << 4), src + ((c >> 5) << 10) + ((c & 31) << 2));
        asm volatile("cp.async.commit_group;\n" ::: "memory");
    };

    // ---- accumulators ----
    unsigned long long acc[32];
    #pragma unroll
    for (int i = 0; i < 32; i++) acc[i] = 0ull;

    const unsigned* iwp = (const unsigned*)(sidx) + sy * 4 + (sx >> 2);

    stage(0); stage(1); stage(2);

    unsigned iw0, iw1, iw2, iw3;
    int cbase;
    {
        iw0 = iwp[0]; iw1 = iwp[4]; iw2 = iwp[8]; iw3 = iwp[12];
        cbase = smeta[0] & 0xffff;
    }

    // -------- pipelined step machinery --------
    unsigned long long va0, va1, vb0, vb1;
    unsigned ra, rb;

    // PROLOG: unconditional load for first pixel into va
#define PROLOG(PX, PY)                                                        \
    asm volatile("{\n\t"                                                      \
        ".reg .u32 ad;\n\t"                                                   \
        "bfe.u32 %2, %3, %4, 8;\n\t"                                          \
        "mad.lo.u32 ad, %2, 512, %5;\n\t"                                     \
        "ld.shared.v2.u64 {%0, %1}, [ad];\n\t"                                \
        "}"                                                                   \
        : "=l"(va0), "=l"(va1), "=r"(ra)                                      \
        : "r"(iw##PY), "n"(8*(PX)), "r"(pvbase))

    // STEPA: consume va (pixel C), prepare vb for pixel N
#define STEPA(CX, CY, NX, NY)                                                 \
    asm volatile("{\n\t"                                                      \
        ".reg .pred p;\n\t .reg .u32 ad;\n\t"                                 \
        "bfe.u32 %4, %7, %8, 8;\n\t"                                          \
        "setp.ne.u32 p, %4, %6;\n\t"                                          \
        "@!p mov.b64 %2, %5;\n\t"                                             \
        "@!p mov.b64 %3, %9;\n\t"                                             \
        "@p mad.lo.u32 ad, %4, 512, %10;\n\t"                                 \
        "@p ld.shared.v2.u64 {%2, %3}, [ad];\n\t"                             \
        "add.rn.f32x2 %0, %0, %5;\n\t"                                        \
        "add.rn.f32x2 %1, %1, %9;\n\t"                                        \
        "}"                                                                   \
        : "+l"(acc[2*((CY)*4+(CX))]), "+l"(acc[2*((CY)*4+(CX))+1]),           \
          "=l"(vb0), "=l"(vb1), "=r"(rb)                                      \
        : "l"(va0), "r"(ra), "r"(iw##NY), "n"(8*(NX)), "l"(va1), "r"(pvbase))

    // STEPB: consume vb, prepare va
#define STEPB(CX, CY, NX, NY)                                                 \
    asm volatile("{\n\t"                                                      \
        ".reg .pred p;\n\t .reg .u32 ad;\n\t"                                 \
        "bfe.u32 %4, %7, %8, 8;\n\t"                                          \
        "setp.ne.u32 p, %4, %6;\n\t"                                          \
        "@!p mov.b64 %2, %5;\n\t"                                             \
        "@!p mov.b64 %3, %9;\n\t"                                             \
        "@p mad.lo.u32 ad, %4, 512, %10;\n\t"                                 \
        "@p ld.shared.v2.u64 {%2, %3}, [ad];\n\t"                             \
        "add.rn.f32x2 %0, %0, %5;\n\t"                                        \
        "add.rn.f32x2 %1, %1, %9;\n\t"                                        \
        "}"                                                                   \
        : "+l"(acc[2*((CY)*4+(CX))]), "+l"(acc[2*((CY)*4+(CX))+1]),           \
          "=l"(va0), "=l"(va1), "=r"(ra)                                      \
        : "l"(vb0), "r"(rb), "r"(iw##NY), "n"(8*(NX)), "l"(vb1), "r"(pvbase))

    // last pixel (odd parity -> vb), adds only
#define STEPLB(CX, CY)                                                        \
    asm volatile("add.rn.f32x2 %0, %0, %1;"                                   \
        : "+l"(acc[2*((CY)*4+(CX))]) : "l"(vb0));                             \
    asm volatile("add.rn.f32x2 %0, %0, %1;"                                   \
        : "+l"(acc[2*((CY)*4+(CX))+1]) : "l"(vb1))

#define CHAIN(X0,Y0,X1,Y1,X2,Y2,X3,Y3,X4,Y4,X5,Y5,X6,Y6,X7,Y7,                \
              X8,Y8,X9,Y9,X10,Y10,X11,Y11,X12,Y12,X13,Y13,X14,Y14,X15,Y15)    \
    PROLOG(X0,Y0);                                                            \
    STEPA(X0,Y0, X1,Y1);   STEPB(X1,Y1, X2,Y2);                               \
    STEPA(X2,Y2, X3,Y3);   STEPB(X3,Y3, X4,Y4);                               \
    STEPA(X4,Y4, X5,Y5);   STEPB(X5,Y5, X6,Y6);                               \
    STEPA(X6,Y6, X7,Y7);   STEPB(X7,Y7, X8,Y8);                               \
    STEPA(X8,Y8, X9,Y9);   STEPB(X9,Y9, X10,Y10);                             \
    STEPA(X10,Y10, X11,Y11); STEPB(X11,Y11, X12,Y12);                         \
    STEPA(X12,Y12, X13,Y13); STEPB(X13,Y13, X14,Y14);                         \
    STEPA(X14,Y14, X15,Y15); STEPLB(X15,Y15)

    #pragma unroll 1
    for (int a = 0; a < NA; a++) {
        if (a < NA - 2)       asm volatile("cp.async.wait_group 2;\n" ::: "memory");
        else if (a == NA - 2) asm volatile("cp.async.wait_group 1;\n" ::: "memory");
        else                  asm volatile("cp.async.wait_group 0;\n" ::: "memory");
        __syncthreads();

        if (a + 3 < NA) stage(a + 3);

        // prefetch next angle's idx words + base
        unsigned niw0 = 0, niw1 = 0, niw2 = 0, niw3 = 0;
        int nbase = 0;
        if (a + 1 < NA) {
            const unsigned* ip = iwp + (a + 1) * 64;
            niw0 = ip[0]; niw1 = ip[4]; niw2 = ip[8]; niw3 = ip[12];
            nbase = smeta[a + 1] & 0xffff;
        }

        unsigned pvbase = (unsigned)__cvta_generic_to_shared(sbuf[a & 3])
                          + (lane << 4) - ((unsigned)cbase << 9);

        if (a >= 23 && a <= 67) {
            CHAIN(0,0, 0,1, 1,0, 2,0, 1,1, 0,2, 0,3, 1,2,
                  2,1, 3,0, 3,1, 2,2, 1,3, 2,3, 3,2, 3,3);
        } else if (a >= 68 && a <= 112) {
            CHAIN(0,0, 1,0, 2,0, 3,0, 3,1, 2,1, 1,1, 0,1,
                  0,2, 1,2, 2,2, 3,2, 3,3, 2,3, 1,3, 0,3);
        } else if (a >= 113 && a <= 157) {
            CHAIN(3,0, 3,1, 2,0, 1,0, 2,1, 3,2, 3,3, 2,2,
                  1,1, 0,0, 0,1, 1,2, 2,3, 1,3, 0,2, 0,3);
        } else {
            CHAIN(0,0, 0,1, 0,2, 0,3, 1,3, 1,2, 1,1, 1,0,
                  2,0, 2,1, 2,2, 2,3, 3,3, 3,2, 3,1, 3,0);
        }

        iw0 = niw0; iw1 = niw1; iw2 = niw2; iw3 = niw3;
        cbase = nbase;
    }
#undef CHAIN
#undef STEPLB
#undef STEPB
#undef STEPA
#undef PROLOG

    // ---- epilogue: float4 stores, 4 consecutive x per channel ----
    const int gx = x0 + sx;
    #pragma unroll
    for (int py = 0; py < 4; py++) {
        int gy = y0 + sy + py;
        float* orow = out + (size_t)gy * WW + gx;
        #pragma unroll
        for (int j = 0; j < 4; j++) {
            float4 o;
            unsigned long long a0 = acc[(py*4+0)*2 + (j>>1)];
            unsigned long long a1 = acc[(py*4+1)*2 + (j>>1)];
            unsigned long long a2 = acc[(py*4+2)*2 + (j>>1)];
            unsigned long long a3 = acc[(py*4+3)*2 + (j>>1)];
            if (j & 1) {
                o.x = __uint_as_float((unsigned)(a0 >> 32));
                o.y = __uint_as_float((unsigned)(a1 >> 32));
                o.z = __uint_as_float((unsigned)(a2 >> 32));
                o.w = __uint_as_float((unsigned)(a3 >> 32));
            } else {
                o.x = __uint_as_float((unsigned)a0);
                o.y = __uint_as_float((unsigned)a1);
                o.z = __uint_as_float((unsigned)a2);
                o.w = __uint_as_float((unsigned)a3);
            }
            *(float4*)(orow + (size_t)(c0 + j) * PIX) = o;
        }
    }
}

// ---------------------------------------------------------------------------
extern "C" void kernel_launch(void* const* d_in, const int* in_sizes, int n_in,
                              void* d_out, int out_size)
{
    const float* hough = (const float*)d_in[0];
    float* out = (float*)d_out;

    tab_kernel<<<1, 256>>>();
    build_idx_kernel<<<dim3(PIX / 256, NA), 256>>>();
    transpose_kernel<<<dim3((AR + 31) / 32, NC / 32), dim3(32, 8)>>>(hough);
    iht_main_kernel<<<dim3(10, 10, 8), 512>>>(out);
}

// round 5
// speedup vs baseline: 9.6393x; 9.6393x over previous
#include <cuda_runtime.h>
#include <cstdint>
#include <cstddef>

// Problem constants
#define NB   8
#define CB   128
#define NC   1024          // NB*CB
#define HH   160
#define WW   160
#define NA   180
#define NR   180
#define AR   (NA*NR)       // 32400
#define PIX  (HH*WW)       // 25600
#define WR   20            // staged rho-window rows (true span <= 18)
#define PH   36            // angles per staging phase
#define NPH  5             // phases per channel chunk (NA = PH*NPH)
#define TPB  256

// Scratch in __device__ globals (no allocation allowed)
__device__ float         g_T[(size_t)AR * NC];       // transposed: T[a][r][nc]
__device__ unsigned char g_idx[(size_t)NA * PIX];    // r index table [a][y][x]
__device__ double        g_tab[2 * NA];              // cos/irho, sin/irho

// ---------------------------------------------------------------------------
// Kernel 0: trig table (fp64, once)
// ---------------------------------------------------------------------------
__global__ void tab_kernel()
{
    int a = threadIdx.x;
    if (a < NA) {
        const double PI = 3.14159265358979323846;
        double th = (double)a * (PI / 180.0);
        double irho = 227.0 / 180.0;   // (int(sqrt(160^2+160^2))+1)/180
        g_tab[a]      = cos(th) / irho;
        g_tab[NA + a] = sin(th) / irho;
    }
}

// ---------------------------------------------------------------------------
// Kernel 1: rho-index table (fp64 FMA-class ops only; matches numpy exactly)
// ---------------------------------------------------------------------------
__global__ void build_idx_kernel()
{
    const int a = blockIdx.y;
    double tc = g_tab[a], ts = g_tab[NA + a];
    int p = blockIdx.x * 256 + threadIdx.x;
    int y = p / WW, x = p - y * WW;
    double v = __dadd_rn(__dmul_rn((double)(x - 80), tc),
                         __dmul_rn((double)(y - 80), ts));
    int r = (int)rint(v) + 90;
    r = min(NR - 1, max(0, r));
    g_idx[(size_t)a * PIX + p] = (unsigned char)r;
}

// ---------------------------------------------------------------------------
// Kernel 2: transpose In[NC][AR] -> T[AR][NC]
// ---------------------------------------------------------------------------
__global__ void transpose_kernel(const float* __restrict__ in)
{
    __shared__ float tile[32][33];
    int ar0 = blockIdx.x * 32;
    int nc0 = blockIdx.y * 32;
    int tx = threadIdx.x;
    int ty = threadIdx.y;
    #pragma unroll
    for (int i = ty; i < 32; i += 8) {
        int ar = ar0 + tx;
        if (ar < AR) tile[i][tx] = in[(size_t)(nc0 + i) * AR + ar];
    }
    __syncthreads();
    #pragma unroll
    for (int i = ty; i < 32; i += 8) {
        int ar = ar0 + i;
        if (ar < AR) g_T[(size_t)ar * NC + nc0 + tx] = tile[tx][i];
    }
}

// ---------------------------------------------------------------------------
// Kernel 3: main inverse-Hough accumulation, pixel-per-lane layout.
//   CTA: 16x16 pixel tile; 256 threads; thread = 1 pixel x 4 channels.
//   Channel loop: 32 chunks of 4 ch (grid.z covers 8 groups of 128).
//   Angles staged in 5 phases of 36; per phase cp.async stages rows
//   [base_a, base_a+20) x 16B of the current chunk, double-buffered and
//   fully overlapped with consumption. Index table transposed+rebased in
//   smem so consume is: 1 LDS.u32 per 4 angles + per angle
//   {bfe, iadd, LDS.128 (broadcast-heavy), 2x add.rn.f32x2}. No serial
//   dependences; ~32 regs -> 3 CTAs/SM (6 warps/SMSP).
// ---------------------------------------------------------------------------
__device__ __forceinline__ void cp16(unsigned smem_addr, const void* gptr)
{
    asm volatile("cp.async.cg.shared.global [%0], [%1], 16;\n"
                 :: "r"(smem_addr), "l"(gptr));
}

__global__ void __launch_bounds__(TPB, 3) iht_main_kernel(float* __restrict__ out)
{
    __shared__ __align__(16) char sbuf[2][PH * WR * 16];     // 2 x 11520 B
    __shared__ __align__(4)  unsigned char sidxt[256 * 184]; // 47104 B
    __shared__ unsigned char sbase[192];

    const int tid = threadIdx.x;
    const int x0 = blockIdx.x * 16;
    const int y0 = blockIdx.y * 16;
    const int cz0 = blockIdx.z * 128;
    const int px = tid & 15, py = tid >> 4;

    // ---- per-angle window base = min of tile corners (affine => corners) ----
    for (int a = tid; a < NA; a += TPB) {
        const unsigned char* s = g_idx + (size_t)a * PIX + y0 * WW + x0;
        int b = min(min((int)s[0], (int)s[15]),
                    min((int)s[15 * WW], (int)s[15 * WW + 15]));
        sbase[a] = (unsigned char)min(b, NR - WR);
    }
    __syncthreads();

    // ---- transposed, rebased idx: sidxt[p*184 + a] = r(a,p) - base[a] ----
    for (int i = tid; i < NA * 64; i += TPB) {
        int a = i >> 6;
        int p4 = (i & 63) << 2;
        int pyy = p4 >> 4, pxx = p4 & 15;
        unsigned wv = *(const unsigned*)(g_idx + (size_t)a * PIX
                                         + (y0 + pyy) * WW + x0 + pxx);
        int b = sbase[a];
        sidxt[(p4 + 0) * 184 + a] = (unsigned char)((wv & 255) - b);
        sidxt[(p4 + 1) * 184 + a] = (unsigned char)(((wv >> 8) & 255) - b);
        sidxt[(p4 + 2) * 184 + a] = (unsigned char)(((wv >> 16) & 255) - b);
        sidxt[(p4 + 3) * 184 + a] = (unsigned char)((wv >> 24) - b);
    }
    __syncthreads();

    // ---- staging: flat phase f in [0,160): chunk=f/5, phase=f%5 ----
    auto stage = [&](int f) {
        int cz = cz0 + (f / NPH) * 4;
        int a0 = (f % NPH) * PH;
        unsigned sd = (unsigned)__cvta_generic_to_shared(sbuf[f & 1]);
        const float* gb = g_T + cz;
        #pragma unroll
        for (int e0 = 0; e0 < PH * WR; e0 += TPB) {
            int e = e0 + tid;
            if (e < PH * WR) {
                int al = e / WR;
                int row = e - al * WR;
                int a = a0 + al;
                int r = (int)sbase[a] + row;
                cp16(sd + (e << 4), gb + ((size_t)a * NR + r) * NC);
            }
        }
        asm volatile("cp.async.commit_group;\n" ::: "memory");
    };

    unsigned long long acc0 = 0ull, acc1 = 0ull;
    const unsigned* iw = (const unsigned*)sidxt + tid * 46;

    stage(0);

    #pragma unroll 1
    for (int f = 0; f < 32 * NPH; f++) {
        asm volatile("cp.async.wait_group 0;\n" ::: "memory");
        __syncthreads();
        if (f + 1 < 32 * NPH) stage(f + 1);   // async; overlaps with consume

        const int phase = f % NPH;
        const char* sb = sbuf[f & 1];
        const unsigned* iwp = iw + phase * 9;

        #pragma unroll
        for (int g = 0; g < 9; g++) {
            unsigned wv = iwp[g];
            #pragma unroll
            for (int k = 0; k < 4; k++) {
                unsigned rel = (wv >> (8 * k)) & 255u;
                const ulonglong2* vp = (const ulonglong2*)
                    (sb + (g * 4 + k) * (WR * 16) + rel * 16);
                ulonglong2 v = *vp;
                asm("add.rn.f32x2 %0, %0, %1;" : "+l"(acc0) : "l"(v.x));
                asm("add.rn.f32x2 %0, %0, %1;" : "+l"(acc1) : "l"(v.y));
            }
        }

        if (phase == NPH - 1) {
            int cz = cz0 + (f / NPH) * 4;
            float* o = out + (size_t)cz * PIX + (y0 + py) * WW + x0 + px;
            o[0 * PIX] = __uint_as_float((unsigned)acc0);
            o[1 * PIX] = __uint_as_float((unsigned)(acc0 >> 32));
            o[2 * PIX] = __uint_as_float((unsigned)acc1);
            o[3 * PIX] = __uint_as_float((unsigned)(acc1 >> 32));
            acc0 = 0ull; acc1 = 0ull;
        }
    }
}

// ---------------------------------------------------------------------------
extern "C" void kernel_launch(void* const* d_in, const int* in_sizes, int n_in,
                              void* d_out, int out_size)
{
    const float* hough = (const float*)d_in[0];
    float* out = (float*)d_out;

    tab_kernel<<<1, 256>>>();
    build_idx_kernel<<<dim3(PIX / 256, NA), 256>>>();
    transpose_kernel<<<dim3((AR + 31) / 32, NC / 32), dim3(32, 8)>>>(hough);
    iht_main_kernel<<<dim3(10, 10, 8), TPB>>>(out);
}